// round 5
// baseline (speedup 1.0000x reference)
#include <cuda_runtime.h>
#include <mma.h>
#include <cstdint>
using namespace nvcuda;

#define NN 16384
#define MM 2048
#define DD 256

#define A_LD   264
#define B_LD   264
#define STG_LD 72

// dynamic SMEM layout (bytes)
#define SM_A    0                  // 128 x 264 f32 = 135168
#define SM_B    135168             // 3 x (16 x 264 f32 = 16896) = 50688
#define SM_STG  185856             // 128 x 72 f32 = 36864
#define SM_ZSQ  222720             // 512 f32 partials
#define SM_ZROW 224768             // 128 f32
#define SM_ES   225280             // 256 f32
#define SM_SMIN 226304             // 256 u32
#define SMEM_TOTAL 227328

__device__ float    g_eT[DD * MM];     // e transposed [k][m], tf32-rounded
__device__ float    g_esq[MM];
__device__ unsigned g_colmin[MM];

// ---------------------------------------------------------------------------
__device__ __forceinline__ float to_tf32(float x) {
    float y; asm("cvt.rna.tf32.f32 %0, %1;" : "=f"(y) : "f"(x)); return y;
}
__device__ __forceinline__ uint32_t smem_u32(const void* p) {
    uint32_t a;
    asm("{ .reg .u64 t; cvta.to.shared.u64 t, %1; cvt.u32.u64 %0, t; }" : "=r"(a) : "l"(p));
    return a;
}
#define CP_ASYNC16(dst, src) \
    asm volatile("cp.async.cg.shared.global [%0], [%1], 16;" :: "r"(dst), "l"(src))
#define CP_COMMIT() asm volatile("cp.async.commit_group;" ::: "memory")
#define CP_WAIT(n)  asm volatile("cp.async.wait_group %0;" :: "n"(n) : "memory")

// ---------------------------------------------------------------------------
__global__ void init_colmin_kernel() {
    int i = blockIdx.x * blockDim.x + threadIdx.x;
    if (i < MM) g_colmin[i] = 0x7f800000u;
}

// e [m][k] -> g_eT [k][m], tf32-rounded. grid (64, 8), block (32, 8)
__global__ void prep_eT_kernel(const float* __restrict__ e) {
    __shared__ float t[32][33];
    int mb = blockIdx.x << 5, kb = blockIdx.y << 5;
    int tx = threadIdx.x, ty = threadIdx.y;
    #pragma unroll
    for (int i = 0; i < 32; i += 8)
        t[ty + i][tx] = e[(size_t)(mb + ty + i) * DD + kb + tx];
    __syncthreads();
    #pragma unroll
    for (int i = 0; i < 32; i += 8)
        g_eT[(size_t)(kb + ty + i) * MM + mb + tx] = to_tf32(t[tx][ty + i]);
}

__global__ void esq_kernel(const float* __restrict__ e) {
    int warp = (blockIdx.x * blockDim.x + threadIdx.x) >> 5;
    int lane = threadIdx.x & 31;
    if (warp >= MM) return;
    const float* row = e + (size_t)warp * DD;
    float s = 0.f;
    #pragma unroll
    for (int i = 0; i < DD / 32; i++) { float v = row[lane + i * 32]; s += v * v; }
    #pragma unroll
    for (int o = 16; o > 0; o >>= 1) s += __shfl_down_sync(0xffffffffu, s, o);
    if (lane == 0) g_esq[warp] = s;
}

// ---------------------------------------------------------------------------
// Persistent fused GEMM + distance + column-min. 128 CTAs x 512 threads.
__global__ void __launch_bounds__(512, 1)
gemm_dist_kernel(const float* __restrict__ z, float* __restrict__ out) {
    extern __shared__ char smem[];
    float* Asm  = (float*)(smem + SM_A);
    float* Bsm  = (float*)(smem + SM_B);
    float* stg  = (float*)(smem + SM_STG);
    float* zsq4 = (float*)(smem + SM_ZSQ);
    float* zrow = (float*)(smem + SM_ZROW);
    float* es   = (float*)(smem + SM_ES);
    unsigned* smin = (unsigned*)(smem + SM_SMIN);
    const uint32_t sbB = smem_u32(Bsm);

    const int tid = threadIdx.x;
    const int wid = tid >> 5;
    const int wy = wid & 3;          // n-dir (4 groups of 32 rows)
    const int wx = wid >> 2;         // m-dir (4 groups of 64 cols)
    const int n0 = blockIdx.x << 7;
    const float* zbase = z + (size_t)(n0 >> 10) * (DD * 1024) + (n0 & 1023);

    // ---- prologue: A = z-tile transposed [n][k] (tf32) + z_sq partials ----
    {
        float zacc = 0.f;
        const int an = tid & 127;
        const int dh = tid >> 7;        // 0..3, 64 d's each
        #pragma unroll 8
        for (int it = 0; it < 64; it++) {
            int d = dh * 64 + it;
            float v = zbase[(size_t)d * 1024 + an];
            zacc += v * v;
            Asm[an * A_LD + d] = to_tf32(v);
        }
        zsq4[tid] = zacc;
        if (tid < 256) smin[tid] = 0x7f800000u;
    }
    __syncthreads();
    if (tid < 128)
        zrow[tid] = zsq4[tid] + zsq4[tid + 128] + zsq4[tid + 256] + zsq4[tid + 384];

    // ---- fragments ----
    wmma::fragment<wmma::accumulator, 16, 16, 8, float> cf[2][4];
    #pragma unroll
    for (int i = 0; i < 2; i++)
        #pragma unroll
        for (int c = 0; c < 4; c++) wmma::fill_fragment(cf[i][c], 0.f);

    // ---- B chunk loader: chunk u -> j = u>>4 (m-chunk 256), kc = u&15 (k 16) ----
    auto issueB = [&](int u) {
        int j = u >> 4, kc = u & 15, buf = u % 3;
        const float* src = g_eT + (size_t)(kc * 16) * MM + j * 256;
        uint32_t dst = sbB + (uint32_t)buf * (16 * B_LD * 4);
        #pragma unroll
        for (int i = 0; i < 2; i++) {
            int op = tid + i * 512;          // 0..1023
            int r = op >> 6, s = op & 63;    // 16 rows x 64 x 16B
            CP_ASYNC16(dst + (uint32_t)(r * B_LD + s * 4) * 4,
                       src + (size_t)r * MM + s * 4);
        }
        CP_COMMIT();
    };

    issueB(0);
    issueB(1);

    for (int u = 0; u < 128; u++) {
        const int j = u >> 4, kc = u & 15, buf = u % 3;
        if (u < 126) { CP_WAIT(1); } else { CP_WAIT(0); }
        __syncthreads();
        if (u + 2 < 128) issueB(u + 2);

        const float* Bb = Bsm + buf * (16 * B_LD);
        #pragma unroll
        for (int ks = 0; ks < 2; ks++) {
            const int k0 = kc * 16 + ks * 8;
            wmma::fragment<wmma::matrix_a, 16, 16, 8, wmma::precision::tf32, wmma::row_major> af[2];
            wmma::fragment<wmma::matrix_b, 16, 16, 8, wmma::precision::tf32, wmma::row_major> bf[4];
            #pragma unroll
            for (int i = 0; i < 2; i++)
                wmma::load_matrix_sync(af[i], Asm + (wy * 32 + 16 * i) * A_LD + k0, A_LD);
            #pragma unroll
            for (int c = 0; c < 4; c++)
                wmma::load_matrix_sync(bf[c], Bb + (ks * 8) * B_LD + wx * 64 + 16 * c, B_LD);
            #pragma unroll
            for (int i = 0; i < 2; i++)
                #pragma unroll
                for (int c = 0; c < 4; c++)
                    wmma::mma_sync(cf[i][c], af[i], bf[c], cf[i][c]);
        }

        if (kc == 15) {
            // ---------------- epilogue for m-chunk j (256 wide) ----------------
            if (tid < 256) es[tid] = g_esq[j * 256 + tid];

            #pragma unroll 1
            for (int q = 0; q < 4; q++) {
                __syncthreads();
                if (wx == q) {
                    #pragma unroll
                    for (int i = 0; i < 2; i++)
                        #pragma unroll
                        for (int c = 0; c < 4; c++)
                            wmma::store_matrix_sync(stg + (wy * 32 + 16 * i) * STG_LD + 16 * c,
                                                    cf[i][c], STG_LD, wmma::mem_row_major);
                }
                __syncthreads();

                // pass 1: distance + coalesced store (4 threads per 256-wide row slab)
                {
                    const int r = tid >> 2;
                    const int c0 = (tid & 3) * 16;
                    const float zr = zrow[r];
                    float* op = out + (size_t)(n0 + r) * MM + j * 256 + q * 64 + c0;
                    #pragma unroll
                    for (int t = 0; t < 4; t++) {
                        float4 cv = *(const float4*)&stg[r * STG_LD + c0 + t * 4];
                        float4 dv;
                        dv.x = fmaxf(fmaf(-2.f, cv.x, zr + es[q * 64 + c0 + t * 4 + 0]), 0.f);
                        dv.y = fmaxf(fmaf(-2.f, cv.y, zr + es[q * 64 + c0 + t * 4 + 1]), 0.f);
                        dv.z = fmaxf(fmaf(-2.f, cv.z, zr + es[q * 64 + c0 + t * 4 + 2]), 0.f);
                        dv.w = fmaxf(fmaf(-2.f, cv.w, zr + es[q * 64 + c0 + t * 4 + 3]), 0.f);
                        *(float4*)(op + t * 4) = dv;
                    }
                }
                // pass 2: column mins (row-wise LDS across lanes, conflict-free)
                {
                    const int col = tid & 63;
                    const int rs = tid >> 6;            // 8 groups x 16 rows
                    const float ec = es[q * 64 + col];
                    float mn = __int_as_float(0x7f800000);
                    #pragma unroll
                    for (int t = 0; t < 16; t++) {
                        int rr = rs * 16 + t;
                        float c = stg[rr * STG_LD + col];
                        float d = fmaxf(fmaf(-2.f, c, zrow[rr] + ec), 0.f);
                        mn = fminf(mn, d);
                    }
                    atomicMin(&smin[q * 64 + col], __float_as_uint(mn));
                }
            }
            __syncthreads();
            if (tid < 256) {
                atomicMin(&g_colmin[j * 256 + tid], smin[tid]);
                smin[tid] = 0x7f800000u;
            }

            #pragma unroll
            for (int i = 0; i < 2; i++)
                #pragma unroll
                for (int c = 0; c < 4; c++) wmma::fill_fragment(cf[i][c], 0.f);
        }
    }
}

// ---------------------------------------------------------------------------
__global__ void loss_kernel(float* __restrict__ out_loss) {
    __shared__ float partial[256];
    int tid = threadIdx.x;
    float s = 0.f;
    for (int i = tid; i < MM; i += 256) s += __uint_as_float(g_colmin[i]);
    partial[tid] = s;
    __syncthreads();
    for (int o = 128; o > 0; o >>= 1) {
        if (tid < o) partial[tid] += partial[tid + o];
        __syncthreads();
    }
    if (tid == 0) out_loss[0] = partial[0] / (float)MM;
}

// ---------------------------------------------------------------------------
extern "C" void kernel_launch(void* const* d_in, const int* in_sizes, int n_in,
                              void* d_out, int out_size) {
    const float* z = (const float*)d_in[0];
    const float* e = (const float*)d_in[1];
    float* out = (float*)d_out;

    cudaFuncSetAttribute(gemm_dist_kernel,
                         cudaFuncAttributeMaxDynamicSharedMemorySize, SMEM_TOTAL);

    init_colmin_kernel<<<(MM + 255) / 256, 256>>>();
    prep_eT_kernel<<<dim3(MM / 32, DD / 32), dim3(32, 8)>>>(e);
    esq_kernel<<<(MM * 32 + 255) / 256, 256>>>(e);

    gemm_dist_kernel<<<128, 512, SMEM_TOTAL>>>(z, out);

    loss_kernel<<<1, 256>>>(out + (size_t)NN * MM);
}

// round 8
// speedup vs baseline: 1.7001x; 1.7001x over previous
#include <cuda_runtime.h>
#include <cstdint>

#define NN 16384
#define MM 2048
#define DD 256

#define STG_LD 144

// dynamic SMEM layout (bytes)
#define SM_A    0                  // A': 8192 uint4 = 131072
#define SM_B    131072             // 3 stages x 512 uint4 (8KB) = 24576
#define SM_STG  155648             // 128 x 144 words = 73728
#define SM_ZROW 229376             // 128 f32
#define SM_ES   229888             // 128 f32
#define SM_SMIN 230400             // 128 u32
#define SMEM_TOTAL 230912

__device__ __align__(16) float g_eB[DD * MM];   // fragment-packed B (tf32)
__device__ float    g_esq[MM];
__device__ unsigned g_colmin[MM];

// ---------------------------------------------------------------------------
__device__ __forceinline__ float to_tf32(float x) {
    float y; asm("cvt.rna.tf32.f32 %0, %1;" : "=f"(y) : "f"(x)); return y;
}
__device__ __forceinline__ uint32_t smem_u32(const void* p) {
    uint32_t a;
    asm("{ .reg .u64 t; cvta.to.shared.u64 t, %1; cvt.u32.u64 %0, t; }" : "=r"(a) : "l"(p));
    return a;
}
#define CP_ASYNC16(dst, src) \
    asm volatile("cp.async.cg.shared.global [%0], [%1], 16;" :: "r"(dst), "l"(src))
#define CP_COMMIT() asm volatile("cp.async.commit_group;" ::: "memory")
#define CP_WAIT(n)  asm volatile("cp.async.wait_group %0;" :: "n"(n) : "memory")

__device__ __forceinline__ void mma_tf32(float4& d, const uint4& a, uint32_t b0, uint32_t b1) {
    asm volatile("mma.sync.aligned.m16n8k8.row.col.f32.tf32.tf32.f32 "
        "{%0,%1,%2,%3}, {%4,%5,%6,%7}, {%8,%9}, {%0,%1,%2,%3};"
        : "+f"(d.x), "+f"(d.y), "+f"(d.z), "+f"(d.w)
        : "r"(a.x), "r"(a.y), "r"(a.z), "r"(a.w), "r"(b0), "r"(b1));
}

// ---------------------------------------------------------------------------
__global__ void init_colmin_kernel() {
    int i = blockIdx.x * blockDim.x + threadIdx.x;
    if (i < MM) g_colmin[i] = 0x7f800000u;
}

// Pack e fragment-major (PTX m16n8k8.tf32 B layout): uint4 at
// ((j*16+kc)*128 + n)*4 + c = tf32{ e[.][16kc+c], [c+4], [c+8], [c+12] }
__global__ void prep_eB_kernel(const float* __restrict__ e) {
    int gid = blockIdx.x * blockDim.x + threadIdx.x;   // uint4 index
    if (gid >= MM * DD / 4) return;
    int c  = gid & 3;
    int n  = (gid >> 2) & 127;
    int kc = (gid >> 9) & 15;
    int j  = gid >> 13;
    const float* row = e + (size_t)(j * 128 + n) * DD + kc * 16;
    float4 v;
    v.x = to_tf32(row[c]);
    v.y = to_tf32(row[c + 4]);
    v.z = to_tf32(row[c + 8]);
    v.w = to_tf32(row[c + 12]);
    ((float4*)g_eB)[gid] = v;
}

__global__ void esq_kernel(const float* __restrict__ e) {
    int warp = (blockIdx.x * blockDim.x + threadIdx.x) >> 5;
    int lane = threadIdx.x & 31;
    if (warp >= MM) return;
    const float* row = e + (size_t)warp * DD;
    float s = 0.f;
    #pragma unroll
    for (int i = 0; i < DD / 32; i++) { float v = row[lane + i * 32]; s += v * v; }
    #pragma unroll
    for (int o = 16; o > 0; o >>= 1) s += __shfl_down_sync(0xffffffffu, s, o);
    if (lane == 0) g_esq[warp] = s;
}

// ---------------------------------------------------------------------------
// Persistent fused GEMM + distance + column-min. 128 CTAs x 512 threads.
__global__ void __launch_bounds__(512, 1)
gemm_dist_kernel(const float* __restrict__ z, float* __restrict__ out) {
    extern __shared__ char smem[];
    uint4* Ash = (uint4*)(smem + SM_A);
    uint4* Bsh = (uint4*)(smem + SM_B);
    float* stg  = (float*)(smem + SM_STG);
    float* zrow = (float*)(smem + SM_ZROW);
    float* es   = (float*)(smem + SM_ES);
    unsigned* smin = (unsigned*)(smem + SM_SMIN);
    const uint32_t sbB = smem_u32(Bsh);

    const int tid = threadIdx.x;
    const int wid = tid >> 5;
    const int lane = tid & 31;
    const int wy = wid & 3;          // n-dir: rows wy*32..+31
    const int wx = wid >> 2;         // m-dir: cols wx*32..+31
    const int n0 = blockIdx.x << 7;
    const float* zbase = z + (size_t)(n0 >> 10) * (DD * 1024) + (n0 & 1023);

    // ---- B chunk loader: 512 uint4 per chunk, one per thread ----
    auto issueB = [&](int u) {
        int buf = u % 3;
        CP_ASYNC16(sbB + (uint32_t)(buf * 512 + tid) * 16,
                   (const char*)g_eB + ((size_t)u * 512 + tid) * 16);
        CP_COMMIT();
    };
    issueB(0);
    issueB(1);

    // ---- prologue 1: z_sq (coalesced); partials staged in stg ----
    {
        float zacc = 0.f;
        const int an = tid & 127;
        const int dh = tid >> 7;
        #pragma unroll 8
        for (int it = 0; it < 64; it++) {
            float v = zbase[(size_t)(dh * 64 + it) * 1024 + an];
            zacc += v * v;
        }
        stg[tid] = zacc;
    }
    __syncthreads();
    if (tid < 128) {
        zrow[tid] = stg[tid] + stg[tid + 128] + stg[tid + 256] + stg[tid + 384];
        smin[tid] = 0x7f800000u;
    }
    __syncthreads();

    // ---- prologue 2: build A' fragment-major (PTX tf32 A layout) ----
    for (int s = 0; s < 4; s++) {
        #pragma unroll
        for (int it = 0; it < 4; it++) {
            int uu = it * 512 + tid;
            int dp = uu >> 5, i4 = (uu & 31) << 2;
            float4 v = *(const float4*)(zbase + (size_t)(s * 64 + dp) * 1024 + i4);
            *(float4*)(stg + dp * STG_LD + i4) = v;
        }
        __syncthreads();
        #pragma unroll
        for (int it = 0; it < 4; it++) {
            int f = it * 512 + tid;
            int ln = f & 31, ksl = (f >> 5) & 7, rbg = f >> 8;
            int rr = rbg * 16 + (ln >> 2);
            int c  = ln & 3;
            const float* p0 = stg + (ksl * 8 + c) * STG_LD + rr;       // k = c
            const float* p1 = stg + (ksl * 8 + c + 4) * STG_LD + rr;   // k = c+4
            uint4 a;
            a.x = __float_as_uint(to_tf32(p0[0]));   // a0 = (rr,   c)
            a.y = __float_as_uint(to_tf32(p0[8]));   // a1 = (rr+8, c)
            a.z = __float_as_uint(to_tf32(p1[0]));   // a2 = (rr,   c+4)
            a.w = __float_as_uint(to_tf32(p1[8]));   // a3 = (rr+8, c+4)
            Ash[((rbg * 32 + s * 8 + ksl) * 32) + ln] = a;
        }
        __syncthreads();
    }

    // ---- accumulators: warp tile 32 x 32 (2 rowblocks x 4 n-frags) ----
    float4 acc[2][4];
    #pragma unroll
    for (int i = 0; i < 2; i++)
        #pragma unroll
        for (int nf = 0; nf < 4; nf++) acc[i][nf] = make_float4(0.f, 0.f, 0.f, 0.f);

    const int a_base = (wy * 2) * 32 * 32 + lane;
    const int b_base = (wx * 32 + (lane >> 2)) * 4 + (lane & 3);

    for (int u = 0; u < 256; u++) {
        const int kc = u & 15, buf = u % 3;
        if (u < 254) { CP_WAIT(1); } else { CP_WAIT(0); }
        __syncthreads();
        if (u + 2 < 256) issueB(u + 2);

        // fragment loads: all conflict-free LDS.128
        uint4 afr[2][2], bfr[4];
        #pragma unroll
        for (int i = 0; i < 2; i++)
            #pragma unroll
            for (int ii = 0; ii < 2; ii++)
                afr[i][ii] = Ash[a_base + i * 1024 + (kc * 2 + ii) * 32];
        #pragma unroll
        for (int nf = 0; nf < 4; nf++)
            bfr[nf] = Bsh[buf * 512 + b_base + nf * 32];

        #pragma unroll
        for (int i = 0; i < 2; i++)
            #pragma unroll
            for (int nf = 0; nf < 4; nf++) {
                mma_tf32(acc[i][nf], afr[i][0], bfr[nf].x, bfr[nf].y);
                mma_tf32(acc[i][nf], afr[i][1], bfr[nf].z, bfr[nf].w);
            }

        if (kc == 15) {
            // ---------------- epilogue for m-chunk j (128 wide) ----------------
            const int j = u >> 4;
            if (tid < 128) es[tid] = g_esq[j * 128 + tid];

            // STS C frags (no skew; STG_LD=144)
            #pragma unroll
            for (int i = 0; i < 2; i++) {
                int row = wy * 32 + i * 16 + (lane >> 2);
                #pragma unroll
                for (int nf = 0; nf < 4; nf++) {
                    int colb = wx * 32 + nf * 8 + (lane & 3) * 2;
                    float* p = stg + colb;
                    *(float2*)(p + row * STG_LD)       = make_float2(acc[i][nf].x, acc[i][nf].y);
                    *(float2*)(p + (row + 8) * STG_LD) = make_float2(acc[i][nf].z, acc[i][nf].w);
                    acc[i][nf] = make_float4(0.f, 0.f, 0.f, 0.f);
                }
            }
            __syncthreads();

            // pass 1: distance + coalesced STG
            {
                const int r = tid >> 2;
                const int c0 = (tid & 3) * 4;
                const float zr = zrow[r];
                const float* sr = stg + r * STG_LD;
                float* op = out + (size_t)(n0 + r) * MM + j * 128;
                #pragma unroll
                for (int jq = 0; jq < 8; jq++) {
                    int col = c0 + jq * 16;
                    float4 cv = *(const float4*)(sr + col);
                    float4 dv;
                    dv.x = fmaxf(fmaf(-2.f, cv.x, zr + es[col + 0]), 0.f);
                    dv.y = fmaxf(fmaf(-2.f, cv.y, zr + es[col + 1]), 0.f);
                    dv.z = fmaxf(fmaf(-2.f, cv.z, zr + es[col + 2]), 0.f);
                    dv.w = fmaxf(fmaf(-2.f, cv.w, zr + es[col + 3]), 0.f);
                    *(float4*)(op + col) = dv;
                }
            }
            // pass 2: column mins (stg read-only; no barrier needed vs pass1)
            {
                const int col = tid & 127;
                const int rs = tid >> 7;
                const float ec = es[col];
                const float* sc = stg + col;
                float mn = __int_as_float(0x7f800000);
                #pragma unroll
                for (int t = 0; t < 32; t++) {
                    int rr = rs * 32 + t;
                    float cvv = sc[rr * STG_LD];
                    mn = fminf(mn, fmaxf(fmaf(-2.f, cvv, zrow[rr] + ec), 0.f));
                }
                atomicMin(&smin[col], __float_as_uint(mn));
            }
            __syncthreads();
            if (tid < 128) {
                atomicMin(&g_colmin[j * 128 + tid], smin[tid]);
                smin[tid] = 0x7f800000u;
            }
        }
    }
}

// ---------------------------------------------------------------------------
__global__ void loss_kernel(float* __restrict__ out_loss) {
    __shared__ float partial[256];
    int tid = threadIdx.x;
    float s = 0.f;
    for (int i = tid; i < MM; i += 256) s += __uint_as_float(g_colmin[i]);
    partial[tid] = s;
    __syncthreads();
    for (int o = 128; o > 0; o >>= 1) {
        if (tid < o) partial[tid] += partial[tid + o];
        __syncthreads();
    }
    if (tid == 0) out_loss[0] = partial[0] / (float)MM;
}

// ---------------------------------------------------------------------------
extern "C" void kernel_launch(void* const* d_in, const int* in_sizes, int n_in,
                              void* d_out, int out_size) {
    const float* z = (const float*)d_in[0];
    const float* e = (const float*)d_in[1];
    float* out = (float*)d_out;

    cudaFuncSetAttribute(gemm_dist_kernel,
                         cudaFuncAttributeMaxDynamicSharedMemorySize, SMEM_TOTAL);

    init_colmin_kernel<<<(MM + 255) / 256, 256>>>();
    prep_eB_kernel<<<(MM * DD / 4 + 255) / 256, 256>>>(e);
    esq_kernel<<<(MM * 32 + 255) / 256, 256>>>(e);

    gemm_dist_kernel<<<128, 512, SMEM_TOTAL>>>(z, out);

    loss_kernel<<<1, 256>>>(out + (size_t)NN * MM);
}

// round 9
// speedup vs baseline: 1.9077x; 1.1221x over previous
#include <cuda_runtime.h>
#include <cstdint>

#define NN 16384
#define MM 2048
#define DD 256

// dynamic SMEM layout (bytes)
#define SM_A     0                 // A': 8192 uint4 = 131072
#define SM_B     131072            // 3 stages x 1024 uint4 (16KB) = 49152
#define SM_ZPART 180224            // 512 f32
#define SM_ZROW  182272            // 128 f32
#define SMEM_TOTAL 182784

__device__ __align__(16) float g_eB[DD * MM];   // fragment-packed B (tf32)
__device__ float    g_esq[MM];
__device__ unsigned g_colmin[MM];

// ---------------------------------------------------------------------------
__device__ __forceinline__ float to_tf32(float x) {
    float y; asm("cvt.rna.tf32.f32 %0, %1;" : "=f"(y) : "f"(x)); return y;
}
__device__ __forceinline__ uint32_t smem_u32(const void* p) {
    uint32_t a;
    asm("{ .reg .u64 t; cvta.to.shared.u64 t, %1; cvt.u32.u64 %0, t; }" : "=r"(a) : "l"(p));
    return a;
}
#define CP_ASYNC16(dst, src) \
    asm volatile("cp.async.cg.shared.global [%0], [%1], 16;" :: "r"(dst), "l"(src))
#define CP_COMMIT() asm volatile("cp.async.commit_group;" ::: "memory")
#define CP_WAIT(n)  asm volatile("cp.async.wait_group %0;" :: "n"(n) : "memory")
#define RED_MIN_U32(ptr, val) \
    asm volatile("red.global.min.u32 [%0], %1;" :: "l"(ptr), "r"(val) : "memory")

__device__ __forceinline__ void mma_tf32(float4& d, const uint4& a, uint32_t b0, uint32_t b1) {
    asm volatile("mma.sync.aligned.m16n8k8.row.col.f32.tf32.tf32.f32 "
        "{%0,%1,%2,%3}, {%4,%5,%6,%7}, {%8,%9}, {%0,%1,%2,%3};"
        : "+f"(d.x), "+f"(d.y), "+f"(d.z), "+f"(d.w)
        : "r"(a.x), "r"(a.y), "r"(a.z), "r"(a.w), "r"(b0), "r"(b1));
}

// ---------------------------------------------------------------------------
__global__ void init_colmin_kernel() {
    int i = blockIdx.x * blockDim.x + threadIdx.x;
    if (i < MM) g_colmin[i] = 0x7f800000u;
}

// Pack e fragment-major (PTX m16n8k8.tf32 B layout): uint4 at
// ((j*16+kc)*128 + n)*4 + c = tf32{ e[.][16kc+c], [c+4], [c+8], [c+12] }
__global__ void prep_eB_kernel(const float* __restrict__ e) {
    int gid = blockIdx.x * blockDim.x + threadIdx.x;
    if (gid >= MM * DD / 4) return;
    int c  = gid & 3;
    int n  = (gid >> 2) & 127;
    int kc = (gid >> 9) & 15;
    int j  = gid >> 13;
    const float* row = e + (size_t)(j * 128 + n) * DD + kc * 16;
    float4 v;
    v.x = to_tf32(row[c]);
    v.y = to_tf32(row[c + 4]);
    v.z = to_tf32(row[c + 8]);
    v.w = to_tf32(row[c + 12]);
    ((float4*)g_eB)[gid] = v;
}

__global__ void esq_kernel(const float* __restrict__ e) {
    int warp = (blockIdx.x * blockDim.x + threadIdx.x) >> 5;
    int lane = threadIdx.x & 31;
    if (warp >= MM) return;
    const float* row = e + (size_t)warp * DD;
    float s = 0.f;
    #pragma unroll
    for (int i = 0; i < DD / 32; i++) { float v = row[lane + i * 32]; s += v * v; }
    #pragma unroll
    for (int o = 16; o > 0; o >>= 1) s += __shfl_down_sync(0xffffffffu, s, o);
    if (lane == 0) g_esq[warp] = s;
}

// ---------------------------------------------------------------------------
// Persistent fused GEMM + distance + column-min. 128 CTAs x 512 threads.
__global__ void __launch_bounds__(512, 1)
gemm_dist_kernel(const float* __restrict__ z, float* __restrict__ out) {
    extern __shared__ char smem[];
    uint4* Ash   = (uint4*)(smem + SM_A);
    uint4* Bsh   = (uint4*)(smem + SM_B);
    float* zpart = (float*)(smem + SM_ZPART);
    float* zrow  = (float*)(smem + SM_ZROW);
    const uint32_t sbB = smem_u32(Bsh);

    const int tid = threadIdx.x;
    const int wid = tid >> 5;
    const int lane = tid & 31;
    const int wy = wid & 3;          // n-dir: rows wy*32..+31
    const int wx = wid >> 2;         // m-dir: cols wx*32..+31
    const int n0 = blockIdx.x << 7;
    const float* zbase = z + (size_t)(n0 >> 10) * (DD * 1024) + (n0 & 1023);

    // ---- B chunk loader: k32 chunks, 1024 uint4, 2 per thread ----
    auto issueB = [&](int u) {
        int buf = u % 3;
        const char* src = (const char*)g_eB + (size_t)u * 16384;
        uint32_t dst = sbB + (uint32_t)buf * 16384;
        CP_ASYNC16(dst + (uint32_t)tid * 16,         src + (size_t)tid * 16);
        CP_ASYNC16(dst + (uint32_t)(tid + 512) * 16, src + (size_t)(tid + 512) * 16);
        CP_COMMIT();
    };
    issueB(0);
    issueB(1);

    // ---- prologue 1: z_sq (coalesced partials) ----
    {
        float zacc = 0.f;
        const int an = tid & 127;
        const int dh = tid >> 7;
        #pragma unroll 8
        for (int it = 0; it < 64; it++) {
            float v = zbase[(size_t)(dh * 64 + it) * 1024 + an];
            zacc += v * v;
        }
        zpart[tid] = zacc;
    }
    __syncthreads();
    if (tid < 128)
        zrow[tid] = zpart[tid] + zpart[tid + 128] + zpart[tid + 256] + zpart[tid + 384];

    // ---- prologue 2: build A' fragment-major (PTX tf32 A layout), direct LDG ----
    #pragma unroll 4
    for (int it = 0; it < 16; it++) {
        int f = it * 512 + tid;
        int ln = f & 31, kstep = (f >> 5) & 31, rbg = f >> 10;
        int rr = rbg * 16 + (ln >> 2);
        int d0 = kstep * 8 + (ln & 3);
        uint4 a;
        a.x = __float_as_uint(to_tf32(__ldg(zbase + (size_t)d0 * 1024 + rr)));
        a.y = __float_as_uint(to_tf32(__ldg(zbase + (size_t)d0 * 1024 + rr + 8)));
        a.z = __float_as_uint(to_tf32(__ldg(zbase + (size_t)(d0 + 4) * 1024 + rr)));
        a.w = __float_as_uint(to_tf32(__ldg(zbase + (size_t)(d0 + 4) * 1024 + rr + 8)));
        Ash[(rbg * 32 + kstep) * 32 + ln] = a;
    }
    __syncthreads();

    // ---- accumulators: warp tile 32 x 32 ----
    float4 acc[2][4];
    #pragma unroll
    for (int i = 0; i < 2; i++)
        #pragma unroll
        for (int nf = 0; nf < 4; nf++) acc[i][nf] = make_float4(0.f, 0.f, 0.f, 0.f);

    const int a_base = (wy * 2) * 1024 + lane;
    const int b_base = (wx * 32 + (lane >> 2)) * 4 + (lane & 3);
    const int r_lo = (lane >> 2);

    for (int u = 0; u < 128; u++) {
        const int q = u & 7;             // k32 quarter within j
        const int buf = u % 3;
        if (u < 126) { CP_WAIT(1); } else { CP_WAIT(0); }
        __syncthreads();
        if (u + 2 < 128) issueB(u + 2);

        // B fragments: 2 k16-halves (all conflict-free LDS.128)
        uint4 bfr0[4], bfr1[4];
        #pragma unroll
        for (int nf = 0; nf < 4; nf++) {
            bfr0[nf] = Bsh[buf * 1024 + b_base + nf * 32];
            bfr1[nf] = Bsh[buf * 1024 + 512 + b_base + nf * 32];
        }
        #pragma unroll
        for (int i = 0; i < 2; i++) {
            uint4 af[4];
            #pragma unroll
            for (int ks = 0; ks < 4; ks++)
                af[ks] = Ash[a_base + i * 1024 + (q * 4 + ks) * 32];
            #pragma unroll
            for (int nf = 0; nf < 4; nf++) {
                mma_tf32(acc[i][nf], af[0], bfr0[nf].x, bfr0[nf].y);
                mma_tf32(acc[i][nf], af[1], bfr0[nf].z, bfr0[nf].w);
                mma_tf32(acc[i][nf], af[2], bfr1[nf].x, bfr1[nf].y);
                mma_tf32(acc[i][nf], af[3], bfr1[nf].z, bfr1[nf].w);
            }
        }

        if (q == 7) {
            // ------- register-direct epilogue for m-chunk j (no barriers) -------
            const int j = u >> 3;
            float mn[4][2];
            #pragma unroll
            for (int i = 0; i < 2; i++) {
                const float zr0 = zrow[wy * 32 + i * 16 + r_lo];
                const float zr1 = zrow[wy * 32 + i * 16 + r_lo + 8];
                float* orow0 = out + (size_t)(n0 + wy * 32 + i * 16 + r_lo) * MM + j * 128;
                float* orow1 = orow0 + (size_t)8 * MM;
                #pragma unroll
                for (int nf = 0; nf < 4; nf++) {
                    const int col = wx * 32 + nf * 8 + (lane & 3) * 2;
                    float2 ev = *(const float2*)(g_esq + j * 128 + col);
                    float4 a = acc[i][nf];
                    float d00 = fmaxf(fmaf(-2.f, a.x, zr0 + ev.x), 0.f);
                    float d01 = fmaxf(fmaf(-2.f, a.y, zr0 + ev.y), 0.f);
                    float d10 = fmaxf(fmaf(-2.f, a.z, zr1 + ev.x), 0.f);
                    float d11 = fmaxf(fmaf(-2.f, a.w, zr1 + ev.y), 0.f);
                    *(float2*)(orow0 + col) = make_float2(d00, d01);
                    *(float2*)(orow1 + col) = make_float2(d10, d11);
                    float m0 = fminf(d00, d10), m1 = fminf(d01, d11);
                    if (i == 0) { mn[nf][0] = m0; mn[nf][1] = m1; }
                    else        { mn[nf][0] = fminf(mn[nf][0], m0);
                                  mn[nf][1] = fminf(mn[nf][1], m1); }
                    acc[i][nf] = make_float4(0.f, 0.f, 0.f, 0.f);
                }
            }
            // reduce over lane>>2 (bits 2..4), then lanes 0-3 red.global.min
            #pragma unroll
            for (int nf = 0; nf < 4; nf++) {
                #pragma unroll
                for (int h = 0; h < 2; h++) {
                    float m = mn[nf][h];
                    m = fminf(m, __shfl_xor_sync(0xffffffffu, m, 4));
                    m = fminf(m, __shfl_xor_sync(0xffffffffu, m, 8));
                    m = fminf(m, __shfl_xor_sync(0xffffffffu, m, 16));
                    mn[nf][h] = m;
                }
            }
            if (r_lo == 0) {
                #pragma unroll
                for (int nf = 0; nf < 4; nf++) {
                    const int col = j * 128 + wx * 32 + nf * 8 + (lane & 3) * 2;
                    RED_MIN_U32(&g_colmin[col],     __float_as_uint(mn[nf][0]));
                    RED_MIN_U32(&g_colmin[col + 1], __float_as_uint(mn[nf][1]));
                }
            }
        }
    }
}

// ---------------------------------------------------------------------------
__global__ void loss_kernel(float* __restrict__ out_loss) {
    __shared__ float partial[256];
    int tid = threadIdx.x;
    float s = 0.f;
    for (int i = tid; i < MM; i += 256) s += __uint_as_float(g_colmin[i]);
    partial[tid] = s;
    __syncthreads();
    for (int o = 128; o > 0; o >>= 1) {
        if (tid < o) partial[tid] += partial[tid + o];
        __syncthreads();
    }
    if (tid == 0) out_loss[0] = partial[0] / (float)MM;
}

// ---------------------------------------------------------------------------
extern "C" void kernel_launch(void* const* d_in, const int* in_sizes, int n_in,
                              void* d_out, int out_size) {
    const float* z = (const float*)d_in[0];
    const float* e = (const float*)d_in[1];
    float* out = (float*)d_out;

    cudaFuncSetAttribute(gemm_dist_kernel,
                         cudaFuncAttributeMaxDynamicSharedMemorySize, SMEM_TOTAL);

    init_colmin_kernel<<<(MM + 255) / 256, 256>>>();
    prep_eB_kernel<<<(MM * DD / 4 + 255) / 256, 256>>>(e);
    esq_kernel<<<(MM * 32 + 255) / 256, 256>>>(e);

    gemm_dist_kernel<<<128, 512, SMEM_TOTAL>>>(z, out);

    loss_kernel<<<1, 256>>>(out + (size_t)NN * MM);
}

// round 10
// speedup vs baseline: 2.1766x; 1.1409x over previous
#include <cuda_runtime.h>
#include <cstdint>

#define NN 16384
#define MM 2048
#define DD 256

// 64-row n-tiles, 256 CTAs, 2 CTAs/SM.
// dynamic SMEM layout (bytes)
#define SM_A     0                 // A': 4096 uint4 = 65536
#define SM_B     65536             // 2 stages x 1024 uint4 (16KB) = 32768
#define SM_ZPART 98304             // 256 f32
#define SM_ZROW  99328             // 64 f32
#define SMEM_TOTAL 99584

__device__ __align__(16) float g_eB[DD * MM];   // fragment-packed B (tf32)
__device__ float    g_esq[MM];
__device__ unsigned g_colmin[MM];

// ---------------------------------------------------------------------------
__device__ __forceinline__ float to_tf32(float x) {
    float y; asm("cvt.rna.tf32.f32 %0, %1;" : "=f"(y) : "f"(x)); return y;
}
__device__ __forceinline__ uint32_t smem_u32(const void* p) {
    uint32_t a;
    asm("{ .reg .u64 t; cvta.to.shared.u64 t, %1; cvt.u32.u64 %0, t; }" : "=r"(a) : "l"(p));
    return a;
}
#define CP_ASYNC16(dst, src) \
    asm volatile("cp.async.cg.shared.global [%0], [%1], 16;" :: "r"(dst), "l"(src))
#define CP_COMMIT() asm volatile("cp.async.commit_group;" ::: "memory")
#define CP_WAIT(n)  asm volatile("cp.async.wait_group %0;" :: "n"(n) : "memory")
#define RED_MIN_U32(ptr, val) \
    asm volatile("red.global.min.u32 [%0], %1;" :: "l"(ptr), "r"(val) : "memory")

__device__ __forceinline__ void mma_tf32(float4& d, const uint4& a, uint32_t b0, uint32_t b1) {
    asm volatile("mma.sync.aligned.m16n8k8.row.col.f32.tf32.tf32.f32 "
        "{%0,%1,%2,%3}, {%4,%5,%6,%7}, {%8,%9}, {%0,%1,%2,%3};"
        : "+f"(d.x), "+f"(d.y), "+f"(d.z), "+f"(d.w)
        : "r"(a.x), "r"(a.y), "r"(a.z), "r"(a.w), "r"(b0), "r"(b1));
}

// ---------------------------------------------------------------------------
__global__ void init_colmin_kernel() {
    int i = blockIdx.x * blockDim.x + threadIdx.x;
    if (i < MM) g_colmin[i] = 0x7f800000u;
}

// Pack e fragment-major (PTX m16n8k8.tf32 B layout): uint4 at
// ((j*16+kc)*128 + n)*4 + c = tf32{ e[.][16kc+c], [c+4], [c+8], [c+12] }
__global__ void prep_eB_kernel(const float* __restrict__ e) {
    int gid = blockIdx.x * blockDim.x + threadIdx.x;
    if (gid >= MM * DD / 4) return;
    int c  = gid & 3;
    int n  = (gid >> 2) & 127;
    int kc = (gid >> 9) & 15;
    int j  = gid >> 13;
    const float* row = e + (size_t)(j * 128 + n) * DD + kc * 16;
    float4 v;
    v.x = to_tf32(row[c]);
    v.y = to_tf32(row[c + 4]);
    v.z = to_tf32(row[c + 8]);
    v.w = to_tf32(row[c + 12]);
    ((float4*)g_eB)[gid] = v;
}

__global__ void esq_kernel(const float* __restrict__ e) {
    int warp = (blockIdx.x * blockDim.x + threadIdx.x) >> 5;
    int lane = threadIdx.x & 31;
    if (warp >= MM) return;
    const float* row = e + (size_t)warp * DD;
    float s = 0.f;
    #pragma unroll
    for (int i = 0; i < DD / 32; i++) { float v = row[lane + i * 32]; s += v * v; }
    #pragma unroll
    for (int o = 16; o > 0; o >>= 1) s += __shfl_down_sync(0xffffffffu, s, o);
    if (lane == 0) g_esq[warp] = s;
}

// ---------------------------------------------------------------------------
// Fused GEMM + distance + column-min. 256 CTAs x 256 threads (2 CTAs/SM).
__global__ void __launch_bounds__(256, 2)
gemm_dist_kernel(const float* __restrict__ z, float* __restrict__ out) {
    extern __shared__ char smem[];
    uint4* Ash   = (uint4*)(smem + SM_A);
    uint4* Bsh   = (uint4*)(smem + SM_B);
    float* zpart = (float*)(smem + SM_ZPART);
    float* zrow  = (float*)(smem + SM_ZROW);
    const uint32_t sbB = smem_u32(Bsh);

    const int tid = threadIdx.x;
    const int wid = tid >> 5;
    const int lane = tid & 31;
    const int wy = wid & 1;          // n-dir: rows wy*32..+31
    const int wx = wid >> 1;         // m-dir: cols wx*32..+31
    const int n0 = blockIdx.x << 6;  // 64-row tile; 64 | 1024 -> no batch crossing
    const float* zbase = z + (size_t)(n0 >> 10) * (DD * 1024) + (n0 & 1023);

    // ---- B chunk loader: k32 chunks, 1024 uint4, 4 per thread ----
    auto issueB = [&](int u) {
        int buf = u & 1;
        const char* src = (const char*)g_eB + (size_t)u * 16384;
        uint32_t dst = sbB + (uint32_t)buf * 16384;
        CP_ASYNC16(dst + (uint32_t)tid * 16,         src + (size_t)tid * 16);
        CP_ASYNC16(dst + (uint32_t)(tid + 256) * 16, src + (size_t)(tid + 256) * 16);
        CP_ASYNC16(dst + (uint32_t)(tid + 512) * 16, src + (size_t)(tid + 512) * 16);
        CP_ASYNC16(dst + (uint32_t)(tid + 768) * 16, src + (size_t)(tid + 768) * 16);
        CP_COMMIT();
    };
    issueB(0);

    // ---- prologue 1: z_sq partials ----
    {
        float zacc = 0.f;
        const int an = tid & 63;
        const int dh = tid >> 6;          // 0..3, 64 d's each
        #pragma unroll 8
        for (int it = 0; it < 64; it++) {
            float v = zbase[(size_t)(dh * 64 + it) * 1024 + an];
            zacc += v * v;
        }
        zpart[tid] = zacc;
    }
    __syncthreads();
    if (tid < 64)
        zrow[tid] = zpart[tid] + zpart[tid + 64] + zpart[tid + 128] + zpart[tid + 192];

    // ---- prologue 2: build A' fragment-major (PTX tf32 A layout), direct LDG ----
    #pragma unroll 4
    for (int it = 0; it < 16; it++) {
        int f = it * 256 + tid;
        int ln = f & 31, kstep = (f >> 5) & 31, rbg = f >> 10;   // rbg 0..3
        int rr = rbg * 16 + (ln >> 2);
        int d0 = kstep * 8 + (ln & 3);
        uint4 a;
        a.x = __float_as_uint(to_tf32(__ldg(zbase + (size_t)d0 * 1024 + rr)));
        a.y = __float_as_uint(to_tf32(__ldg(zbase + (size_t)d0 * 1024 + rr + 8)));
        a.z = __float_as_uint(to_tf32(__ldg(zbase + (size_t)(d0 + 4) * 1024 + rr)));
        a.w = __float_as_uint(to_tf32(__ldg(zbase + (size_t)(d0 + 4) * 1024 + rr + 8)));
        Ash[(rbg * 32 + kstep) * 32 + ln] = a;
    }

    // ---- accumulators: warp tile 32 x 32 ----
    float4 acc[2][4];
    #pragma unroll
    for (int i = 0; i < 2; i++)
        #pragma unroll
        for (int nf = 0; nf < 4; nf++) acc[i][nf] = make_float4(0.f, 0.f, 0.f, 0.f);

    const int a_base = (wy * 2) * 1024 + lane;
    const int b_base = (wx * 32 + (lane >> 2)) * 4 + (lane & 3);
    const int r_lo = (lane >> 2);

    for (int u = 0; u < 128; u++) {
        const int q = u & 7;             // k32 quarter within j
        const int buf = u & 1;
        CP_WAIT(0);
        __syncthreads();
        if (u + 1 < 128) issueB(u + 1);

        // B fragments: 2 k16-halves (all conflict-free LDS.128)
        uint4 bfr0[4], bfr1[4];
        #pragma unroll
        for (int nf = 0; nf < 4; nf++) {
            bfr0[nf] = Bsh[buf * 1024 + b_base + nf * 32];
            bfr1[nf] = Bsh[buf * 1024 + 512 + b_base + nf * 32];
        }
        #pragma unroll
        for (int i = 0; i < 2; i++) {
            uint4 af[4];
            #pragma unroll
            for (int ks = 0; ks < 4; ks++)
                af[ks] = Ash[a_base + i * 1024 + (q * 4 + ks) * 32];
            #pragma unroll
            for (int nf = 0; nf < 4; nf++) {
                mma_tf32(acc[i][nf], af[0], bfr0[nf].x, bfr0[nf].y);
                mma_tf32(acc[i][nf], af[1], bfr0[nf].z, bfr0[nf].w);
                mma_tf32(acc[i][nf], af[2], bfr1[nf].x, bfr1[nf].y);
                mma_tf32(acc[i][nf], af[3], bfr1[nf].z, bfr1[nf].w);
            }
        }

        if (q == 7) {
            // ------- register-direct epilogue for m-chunk j (no barriers) -------
            const int j = u >> 3;
            float mn[4][2];
            #pragma unroll
            for (int i = 0; i < 2; i++) {
                const float zr0 = zrow[wy * 32 + i * 16 + r_lo];
                const float zr1 = zrow[wy * 32 + i * 16 + r_lo + 8];
                float* orow0 = out + (size_t)(n0 + wy * 32 + i * 16 + r_lo) * MM + j * 128;
                float* orow1 = orow0 + (size_t)8 * MM;
                #pragma unroll
                for (int nf = 0; nf < 4; nf++) {
                    const int col = wx * 32 + nf * 8 + (lane & 3) * 2;
                    float2 ev = *(const float2*)(g_esq + j * 128 + col);
                    float4 a = acc[i][nf];
                    float d00 = fmaxf(fmaf(-2.f, a.x, zr0 + ev.x), 0.f);
                    float d01 = fmaxf(fmaf(-2.f, a.y, zr0 + ev.y), 0.f);
                    float d10 = fmaxf(fmaf(-2.f, a.z, zr1 + ev.x), 0.f);
                    float d11 = fmaxf(fmaf(-2.f, a.w, zr1 + ev.y), 0.f);
                    *(float2*)(orow0 + col) = make_float2(d00, d01);
                    *(float2*)(orow1 + col) = make_float2(d10, d11);
                    float m0 = fminf(d00, d10), m1 = fminf(d01, d11);
                    if (i == 0) { mn[nf][0] = m0; mn[nf][1] = m1; }
                    else        { mn[nf][0] = fminf(mn[nf][0], m0);
                                  mn[nf][1] = fminf(mn[nf][1], m1); }
                    acc[i][nf] = make_float4(0.f, 0.f, 0.f, 0.f);
                }
            }
            #pragma unroll
            for (int nf = 0; nf < 4; nf++) {
                #pragma unroll
                for (int h = 0; h < 2; h++) {
                    float m = mn[nf][h];
                    m = fminf(m, __shfl_xor_sync(0xffffffffu, m, 4));
                    m = fminf(m, __shfl_xor_sync(0xffffffffu, m, 8));
                    m = fminf(m, __shfl_xor_sync(0xffffffffu, m, 16));
                    mn[nf][h] = m;
                }
            }
            if (r_lo == 0) {
                #pragma unroll
                for (int nf = 0; nf < 4; nf++) {
                    const int col = j * 128 + wx * 32 + nf * 8 + (lane & 3) * 2;
                    RED_MIN_U32(&g_colmin[col],     __float_as_uint(mn[nf][0]));
                    RED_MIN_U32(&g_colmin[col + 1], __float_as_uint(mn[nf][1]));
                }
            }
        }
    }
}

// ---------------------------------------------------------------------------
__global__ void loss_kernel(float* __restrict__ out_loss) {
    __shared__ float partial[256];
    int tid = threadIdx.x;
    float s = 0.f;
    for (int i = tid; i < MM; i += 256) s += __uint_as_float(g_colmin[i]);
    partial[tid] = s;
    __syncthreads();
    for (int o = 128; o > 0; o >>= 1) {
        if (tid < o) partial[tid] += partial[tid + o];
        __syncthreads();
    }
    if (tid == 0) out_loss[0] = partial[0] / (float)MM;
}

// ---------------------------------------------------------------------------
extern "C" void kernel_launch(void* const* d_in, const int* in_sizes, int n_in,
                              void* d_out, int out_size) {
    const float* z = (const float*)d_in[0];
    const float* e = (const float*)d_in[1];
    float* out = (float*)d_out;

    cudaFuncSetAttribute(gemm_dist_kernel,
                         cudaFuncAttributeMaxDynamicSharedMemorySize, SMEM_TOTAL);

    init_colmin_kernel<<<(MM + 255) / 256, 256>>>();
    prep_eB_kernel<<<(MM * DD / 4 + 255) / 256, 256>>>(e);
    esq_kernel<<<(MM * 32 + 255) / 256, 256>>>(e);

    gemm_dist_kernel<<<256, 256, SMEM_TOTAL>>>(z, out);

    loss_kernel<<<1, 256>>>(out + (size_t)NN * MM);
}

// round 11
// speedup vs baseline: 2.2995x; 1.0565x over previous
#include <cuda_runtime.h>
#include <cstdint>

#define NN 16384
#define MM 2048
#define DD 256

// 64-row n-tiles, 256 CTAs, 2 CTAs/SM.
// dynamic SMEM layout (bytes)
#define SM_A     0                 // A': 4096 uint4 = 65536
#define SM_B     65536             // 4 stages x 512 uint4 (8KB) = 32768
#define SM_ZPART 98304             // 256 f32
#define SM_ZROW  99328             // 64 f32
#define SMEM_TOTAL 99584

__device__ __align__(16) float g_eB[DD * MM];   // fragment-packed B (tf32)
__device__ float    g_esq[MM];
__device__ unsigned g_colmin[MM];

// ---------------------------------------------------------------------------
__device__ __forceinline__ float to_tf32(float x) {
    float y; asm("cvt.rna.tf32.f32 %0, %1;" : "=f"(y) : "f"(x)); return y;
}
__device__ __forceinline__ uint32_t smem_u32(const void* p) {
    uint32_t a;
    asm("{ .reg .u64 t; cvta.to.shared.u64 t, %1; cvt.u32.u64 %0, t; }" : "=r"(a) : "l"(p));
    return a;
}
#define CP_ASYNC16(dst, src) \
    asm volatile("cp.async.cg.shared.global [%0], [%1], 16;" :: "r"(dst), "l"(src))
#define CP_COMMIT() asm volatile("cp.async.commit_group;" ::: "memory")
#define CP_WAIT(n)  asm volatile("cp.async.wait_group %0;" :: "n"(n) : "memory")
#define RED_MIN_U32(ptr, val) \
    asm volatile("red.global.min.u32 [%0], %1;" :: "l"(ptr), "r"(val) : "memory")

__device__ __forceinline__ void mma_tf32(float4& d, const uint4& a, uint32_t b0, uint32_t b1) {
    asm volatile("mma.sync.aligned.m16n8k8.row.col.f32.tf32.tf32.f32 "
        "{%0,%1,%2,%3}, {%4,%5,%6,%7}, {%8,%9}, {%0,%1,%2,%3};"
        : "+f"(d.x), "+f"(d.y), "+f"(d.z), "+f"(d.w)
        : "r"(a.x), "r"(a.y), "r"(a.z), "r"(a.w), "r"(b0), "r"(b1));
}

// ---------------------------------------------------------------------------
__global__ void init_colmin_kernel() {
    int i = blockIdx.x * blockDim.x + threadIdx.x;
    if (i < MM) g_colmin[i] = 0x7f800000u;
}

// Pack e fragment-major (PTX m16n8k8.tf32 B layout): uint4 at
// ((j*16+kc)*128 + n)*4 + c = tf32{ e[.][16kc+c], [c+4], [c+8], [c+12] }
__global__ void prep_eB_kernel(const float* __restrict__ e) {
    int gid = blockIdx.x * blockDim.x + threadIdx.x;
    if (gid >= MM * DD / 4) return;
    int c  = gid & 3;
    int n  = (gid >> 2) & 127;
    int kc = (gid >> 9) & 15;
    int j  = gid >> 13;
    const float* row = e + (size_t)(j * 128 + n) * DD + kc * 16;
    float4 v;
    v.x = to_tf32(row[c]);
    v.y = to_tf32(row[c + 4]);
    v.z = to_tf32(row[c + 8]);
    v.w = to_tf32(row[c + 12]);
    ((float4*)g_eB)[gid] = v;
}

__global__ void esq_kernel(const float* __restrict__ e) {
    int warp = (blockIdx.x * blockDim.x + threadIdx.x) >> 5;
    int lane = threadIdx.x & 31;
    if (warp >= MM) return;
    const float* row = e + (size_t)warp * DD;
    float s = 0.f;
    #pragma unroll
    for (int i = 0; i < DD / 32; i++) { float v = row[lane + i * 32]; s += v * v; }
    #pragma unroll
    for (int o = 16; o > 0; o >>= 1) s += __shfl_down_sync(0xffffffffu, s, o);
    if (lane == 0) g_esq[warp] = s;
}

// ---------------------------------------------------------------------------
// Fused GEMM + distance + column-min. 256 CTAs x 256 threads (2 CTAs/SM).
__global__ void __launch_bounds__(256, 2)
gemm_dist_kernel(const float* __restrict__ z, float* __restrict__ out) {
    extern __shared__ char smem[];
    uint4* Ash   = (uint4*)(smem + SM_A);
    uint4* Bsh   = (uint4*)(smem + SM_B);
    float* zpart = (float*)(smem + SM_ZPART);
    float* zrow  = (float*)(smem + SM_ZROW);
    const uint32_t sbB = smem_u32(Bsh);

    const int tid = threadIdx.x;
    const int wid = tid >> 5;
    const int lane = tid & 31;
    const int wy = wid & 1;          // n-dir: rows wy*32..+31
    const int wx = wid >> 1;         // m-dir: cols wx*32..+31
    const int n0 = blockIdx.x << 6;  // 64-row tile
    const float* zbase = z + (size_t)(n0 >> 10) * (DD * 1024) + (n0 & 1023);

    // ---- B chunk loader: k16 chunks (512 uint4), 2 per thread ----
    auto issueB = [&](int u) {
        int buf = u & 3;
        const char* src = (const char*)g_eB + (size_t)u * 8192;
        uint32_t dst = sbB + (uint32_t)buf * 8192;
        CP_ASYNC16(dst + (uint32_t)tid * 16,         src + (size_t)tid * 16);
        CP_ASYNC16(dst + (uint32_t)(tid + 256) * 16, src + (size_t)(tid + 256) * 16);
        CP_COMMIT();
    };
    issueB(0);
    issueB(1);
    issueB(2);

    // ---- prologue 1: z_sq partials ----
    {
        float zacc = 0.f;
        const int an = tid & 63;
        const int dh = tid >> 6;
        #pragma unroll 8
        for (int it = 0; it < 64; it++) {
            float v = zbase[(size_t)(dh * 64 + it) * 1024 + an];
            zacc += v * v;
        }
        zpart[tid] = zacc;
    }
    __syncthreads();
    if (tid < 64)
        zrow[tid] = zpart[tid] + zpart[tid + 64] + zpart[tid + 128] + zpart[tid + 192];

    // ---- prologue 2: build A' fragment-major (PTX tf32 A layout), direct LDG ----
    #pragma unroll 4
    for (int it = 0; it < 16; it++) {
        int f = it * 256 + tid;
        int ln = f & 31, kstep = (f >> 5) & 31, rbg = f >> 10;   // rbg 0..3
        int rr = rbg * 16 + (ln >> 2);
        int d0 = kstep * 8 + (ln & 3);
        uint4 a;
        a.x = __float_as_uint(to_tf32(__ldg(zbase + (size_t)d0 * 1024 + rr)));
        a.y = __float_as_uint(to_tf32(__ldg(zbase + (size_t)d0 * 1024 + rr + 8)));
        a.z = __float_as_uint(to_tf32(__ldg(zbase + (size_t)(d0 + 4) * 1024 + rr)));
        a.w = __float_as_uint(to_tf32(__ldg(zbase + (size_t)(d0 + 4) * 1024 + rr + 8)));
        Ash[(rbg * 32 + kstep) * 32 + ln] = a;
    }

    // ---- accumulators: warp tile 32 x 32 ----
    float4 acc[2][4];
    #pragma unroll
    for (int i = 0; i < 2; i++)
        #pragma unroll
        for (int nf = 0; nf < 4; nf++) acc[i][nf] = make_float4(0.f, 0.f, 0.f, 0.f);

    const int a_base = (wy * 2) * 1024 + lane;
    const int b_base = (wx * 32 + (lane >> 2)) * 4 + (lane & 3);
    const int r_lo = (lane >> 2);

    for (int u = 0; u < 256; u++) {
        const int kc = u & 15;           // k16 chunk within j
        const int buf = u & 3;
        CP_WAIT(2);                       // chunk u complete (issued 3 iters ago)
        __syncthreads();
        if (u + 3 < 256) issueB(u + 3);

        // B fragments (conflict-free LDS.128), then A frags, then MMAs
        uint4 bfr[4];
        #pragma unroll
        for (int nf = 0; nf < 4; nf++)
            bfr[nf] = Bsh[buf * 512 + b_base + nf * 32];

        uint4 af[2][2];
        #pragma unroll
        for (int i = 0; i < 2; i++)
            #pragma unroll
            for (int ks = 0; ks < 2; ks++)
                af[i][ks] = Ash[a_base + i * 1024 + (kc * 2 + ks) * 32];

        #pragma unroll
        for (int i = 0; i < 2; i++)
            #pragma unroll
            for (int nf = 0; nf < 4; nf++) {
                mma_tf32(acc[i][nf], af[i][0], bfr[nf].x, bfr[nf].y);
                mma_tf32(acc[i][nf], af[i][1], bfr[nf].z, bfr[nf].w);
            }

        if (kc == 15) {
            // ------- register-direct epilogue for m-chunk j (no barriers) -------
            const int j = u >> 4;
            float mn[4][2];
            #pragma unroll
            for (int i = 0; i < 2; i++) {
                const float zr0 = zrow[wy * 32 + i * 16 + r_lo];
                const float zr1 = zrow[wy * 32 + i * 16 + r_lo + 8];
                float* orow0 = out + (size_t)(n0 + wy * 32 + i * 16 + r_lo) * MM + j * 128;
                float* orow1 = orow0 + (size_t)8 * MM;
                #pragma unroll
                for (int nf = 0; nf < 4; nf++) {
                    const int col = wx * 32 + nf * 8 + (lane & 3) * 2;
                    float2 ev = *(const float2*)(g_esq + j * 128 + col);
                    float4 a = acc[i][nf];
                    float d00 = fmaxf(fmaf(-2.f, a.x, zr0 + ev.x), 0.f);
                    float d01 = fmaxf(fmaf(-2.f, a.y, zr0 + ev.y), 0.f);
                    float d10 = fmaxf(fmaf(-2.f, a.z, zr1 + ev.x), 0.f);
                    float d11 = fmaxf(fmaf(-2.f, a.w, zr1 + ev.y), 0.f);
                    *(float2*)(orow0 + col) = make_float2(d00, d01);
                    *(float2*)(orow1 + col) = make_float2(d10, d11);
                    float m0 = fminf(d00, d10), m1 = fminf(d01, d11);
                    if (i == 0) { mn[nf][0] = m0; mn[nf][1] = m1; }
                    else        { mn[nf][0] = fminf(mn[nf][0], m0);
                                  mn[nf][1] = fminf(mn[nf][1], m1); }
                    acc[i][nf] = make_float4(0.f, 0.f, 0.f, 0.f);
                }
            }
            #pragma unroll
            for (int nf = 0; nf < 4; nf++) {
                #pragma unroll
                for (int h = 0; h < 2; h++) {
                    float m = mn[nf][h];
                    m = fminf(m, __shfl_xor_sync(0xffffffffu, m, 4));
                    m = fminf(m, __shfl_xor_sync(0xffffffffu, m, 8));
                    m = fminf(m, __shfl_xor_sync(0xffffffffu, m, 16));
                    mn[nf][h] = m;
                }
            }
            if (r_lo == 0) {
                #pragma unroll
                for (int nf = 0; nf < 4; nf++) {
                    const int col = j * 128 + wx * 32 + nf * 8 + (lane & 3) * 2;
                    RED_MIN_U32(&g_colmin[col],     __float_as_uint(mn[nf][0]));
                    RED_MIN_U32(&g_colmin[col + 1], __float_as_uint(mn[nf][1]));
                }
            }
        }
    }
}

// ---------------------------------------------------------------------------
__global__ void loss_kernel(float* __restrict__ out_loss) {
    __shared__ float partial[256];
    int tid = threadIdx.x;
    float s = 0.f;
    for (int i = tid; i < MM; i += 256) s += __uint_as_float(g_colmin[i]);
    partial[tid] = s;
    __syncthreads();
    for (int o = 128; o > 0; o >>= 1) {
        if (tid < o) partial[tid] += partial[tid + o];
        __syncthreads();
    }
    if (tid == 0) out_loss[0] = partial[0] / (float)MM;
}

// ---------------------------------------------------------------------------
extern "C" void kernel_launch(void* const* d_in, const int* in_sizes, int n_in,
                              void* d_out, int out_size) {
    const float* z = (const float*)d_in[0];
    const float* e = (const float*)d_in[1];
    float* out = (float*)d_out;

    cudaFuncSetAttribute(gemm_dist_kernel,
                         cudaFuncAttributeMaxDynamicSharedMemorySize, SMEM_TOTAL);

    init_colmin_kernel<<<(MM + 255) / 256, 256>>>();
    prep_eB_kernel<<<(MM * DD / 4 + 255) / 256, 256>>>(e);
    esq_kernel<<<(MM * 32 + 255) / 256, 256>>>(e);

    gemm_dist_kernel<<<256, 256, SMEM_TOTAL>>>(z, out);

    loss_kernel<<<1, 256>>>(out + (size_t)NN * MM);
}